// round 10
// baseline (speedup 1.0000x reference)
#include <cuda_runtime.h>

#define BB 8
#define CC 64
#define DD 32
#define HH 64
#define WW 64
#define SS (DD*HH*WW)      /* 131072 spatial per batch */
#define PLANE (HH*WW)      /* 4096 */
#define S4 (SS/4)          /* 32768 */

// Scratch: channel-reduced avg/max, layout [B][D][H][W] (8 MB total).
__device__ __align__(16) float g_avg[BB*SS];
__device__ __align__(16) float g_max[BB*SS];

// ---------------------------------------------------------------------------
// Pass 1: channel mean + max. One thread = 4 consecutive w elements (float4).
// At the LTS/HBM throughput cap (~6.7 TB/s achieved) — unchanged.
// ---------------------------------------------------------------------------
__global__ __launch_bounds__(256) void reduce_kernel(const float* __restrict__ x) {
    int tid = blockIdx.x * blockDim.x + threadIdx.x;   // 0 .. 262143
    int b    = tid >> 15;
    int off4 = tid & (S4 - 1);

    const float4* base = reinterpret_cast<const float4*>(x)
                       + (size_t)b * CC * S4 + off4;

    float4 s = make_float4(0.f, 0.f, 0.f, 0.f);
    float4 m = make_float4(-3.402823466e38f, -3.402823466e38f,
                           -3.402823466e38f, -3.402823466e38f);

    #pragma unroll 8
    for (int c = 0; c < CC; ++c) {
        float4 v = __ldg(base + (size_t)c * S4);
        s.x += v.x; s.y += v.y; s.z += v.z; s.w += v.w;
        m.x = fmaxf(m.x, v.x); m.y = fmaxf(m.y, v.y);
        m.z = fmaxf(m.z, v.z); m.w = fmaxf(m.w, v.w);
    }

    const float inv = 1.0f / 64.0f;
    float4 a = make_float4(s.x * inv, s.y * inv, s.z * inv, s.w * inv);

    reinterpret_cast<float4*>(g_avg)[tid] = a;
    reinterpret_cast<float4*>(g_max)[tid] = m;
}

// ---------------------------------------------------------------------------
// Pass 2: 3x3x3 SAME conv (avg,max -> 1 ch) + sigmoid, smem plane tiling.
//
// Block = 256 threads, tile = (h:8, w:64), d-chunk of 8 -> 256 blocks.
// Per d-step the block loads one zero-padded 10x66 halo plane (avg+max) into
// a double-buffered smem tile (1 barrier/step), then every thread accumulates
// that plane's contribution into 3 rotating d-accumulators for a w-pair of
// outputs: 12 LDS + 108 FFMA per array set, NO bound predicates in the hot
// loop. Each input value is loaded from gmem once per block (h-halo 10/8).
// ---------------------------------------------------------------------------
#define TH 8
#define DC 8
#define SMW 68   /* padded smem row: cols 0..65 valid, 66/67 pad */

__global__ __launch_bounds__(256) void conv_kernel(const float* __restrict__ Wt,
                                                   float* __restrict__ out) {
    __shared__ float sA[2][TH + 2][SMW];
    __shared__ float sM[2][TH + 2][SMW];

    int blk = blockIdx.x;        // 0..255
    int ht  = blk & 7;           // h tile index
    int dc  = (blk >> 3) & 3;    // d chunk index
    int b   = blk >> 5;          // batch
    int h0  = ht * TH;
    int d0  = dc * DC;
    int t   = threadIdx.x;

    // 54 weights -> registers. Layout: ci*27 + kd*9 + kh*3 + kw.
    float wt[54];
    #pragma unroll
    for (int i = 0; i < 54; ++i) wt[i] = __ldg(Wt + i);

    const float* ga = g_avg + (size_t)b * SS;
    const float* gm = g_max + (size_t)b * SS;
    float*       ob = out   + (size_t)b * SS;

    int hl = t >> 5;             // 0..7  local h
    int wl = (t & 31) * 2;       // 0..62 local w (pair)

    // rotating accumulators: a0 -> out[p-1], a1 -> out[p]
    float a0x = 0.f, a0y = 0.f, a1x = 0.f, a1y = 0.f;

    for (int p = d0 - 1; p <= d0 + DC; ++p) {
        int buf = (p - (d0 - 1)) & 1;

        // ---- cooperative load of halo plane p (zero-padded) ----
        if ((unsigned)p < (unsigned)DD) {
            const float* pa = ga + p * PLANE;
            const float* pm = gm + p * PLANE;
            #pragma unroll
            for (int i = t; i < (TH + 2) * SMW; i += 256) {
                int r  = i / SMW;
                int c  = i - r * SMW;
                int hh = h0 - 1 + r;
                int ww = c - 1;
                bool ok = ((unsigned)hh < (unsigned)HH) &&
                          ((unsigned)ww < (unsigned)WW);
                int off = hh * WW + ww;
                (&sA[0][0][0])[buf * (TH + 2) * SMW + i] = ok ? __ldg(pa + off) : 0.f;
                (&sM[0][0][0])[buf * (TH + 2) * SMW + i] = ok ? __ldg(pm + off) : 0.f;
            }
        } else {
            #pragma unroll
            for (int i = t; i < (TH + 2) * SMW; i += 256) {
                (&sA[0][0][0])[buf * (TH + 2) * SMW + i] = 0.f;
                (&sM[0][0][0])[buf * (TH + 2) * SMW + i] = 0.f;
            }
        }
        __syncthreads();

        // ---- accumulate plane p: kd=0 -> out[p+1], kd=1 -> out[p], kd=2 -> out[p-1]
        float a2x = 0.f, a2y = 0.f;
        #pragma unroll
        for (int kh = 0; kh < 3; ++kh) {
            #pragma unroll
            for (int kw = 0; kw < 3; ++kw) {
                const int i = kh * 3 + kw;
                // smem col = w_input + 1; center w = wl -> col = wl + kw
                float vax = sA[buf][hl + kh][wl + kw];
                float vay = sA[buf][hl + kh][wl + kw + 1];
                float vmx = sM[buf][hl + kh][wl + kw];
                float vmy = sM[buf][hl + kh][wl + kw + 1];
                a0x = fmaf(vax, wt[18 + i], a0x); a0x = fmaf(vmx, wt[45 + i], a0x);
                a0y = fmaf(vay, wt[18 + i], a0y); a0y = fmaf(vmy, wt[45 + i], a0y);
                a1x = fmaf(vax, wt[ 9 + i], a1x); a1x = fmaf(vmx, wt[36 + i], a1x);
                a1y = fmaf(vay, wt[ 9 + i], a1y); a1y = fmaf(vmy, wt[36 + i], a1y);
                a2x = fmaf(vax, wt[     i], a2x); a2x = fmaf(vmx, wt[27 + i], a2x);
                a2y = fmaf(vay, wt[     i], a2y); a2y = fmaf(vmy, wt[27 + i], a2y);
            }
        }

        if (p >= d0 + 1) {
            int od = p - 1;
            float2 o;
            o.x = 1.0f / (1.0f + __expf(-a0x));
            o.y = 1.0f / (1.0f + __expf(-a0y));
            *reinterpret_cast<float2*>(ob + od * PLANE + (h0 + hl) * WW + wl) = o;
        }
        a0x = a1x; a0y = a1y;
        a1x = a2x; a1y = a2y;
    }
}

extern "C" void kernel_launch(void* const* d_in, const int* in_sizes, int n_in,
                              void* d_out, int out_size) {
    const float* x  = (const float*)d_in[0];   // [8,64,32,64,64] fp32
    const float* Wt = (const float*)d_in[1];   // [1,2,3,3,3]     fp32
    float* out = (float*)d_out;                // [8,1,32,64,64]  fp32
    (void)in_sizes; (void)n_in; (void)out_size;

    reduce_kernel<<<1024, 256>>>(x);
    conv_kernel<<<256, 256>>>(Wt, out);
}

// round 11
// speedup vs baseline: 1.1952x; 1.1952x over previous
#include <cuda_runtime.h>

typedef unsigned long long u64;

#define BB 8
#define CC 64
#define DD 32
#define HH 64
#define WW 64
#define SS (DD*HH*WW)      /* 131072 spatial per batch */
#define PLANE (HH*WW)      /* 4096 */
#define S4 (SS/4)          /* 32768 */

// Scratch: channel-reduced (avg,max) INTERLEAVED as float2, layout [B][D][H][W].
// One 64-bit load fetches both channels; pairs lane-wise with packed f32x2 weights.
__device__ __align__(16) float2 g_am[BB*SS];

// ---------------------------------------------------------------------------
// Pass 1: channel mean + max. One thread = 4 consecutive w elements (float4).
// At the LTS/HBM throughput cap (~6.7 TB/s achieved). Only change vs r7:
// interleaved (avg,max) store — two STG.128, still fully coalesced.
// ---------------------------------------------------------------------------
__global__ __launch_bounds__(256) void reduce_kernel(const float* __restrict__ x) {
    int tid = blockIdx.x * blockDim.x + threadIdx.x;   // 0 .. 262143
    int b    = tid >> 15;
    int off4 = tid & (S4 - 1);

    const float4* base = reinterpret_cast<const float4*>(x)
                       + (size_t)b * CC * S4 + off4;

    float4 s = make_float4(0.f, 0.f, 0.f, 0.f);
    float4 m = make_float4(-3.402823466e38f, -3.402823466e38f,
                           -3.402823466e38f, -3.402823466e38f);

    #pragma unroll 8
    for (int c = 0; c < CC; ++c) {
        float4 v = __ldg(base + (size_t)c * S4);
        s.x += v.x; s.y += v.y; s.z += v.z; s.w += v.w;
        m.x = fmaxf(m.x, v.x); m.y = fmaxf(m.y, v.y);
        m.z = fmaxf(m.z, v.z); m.w = fmaxf(m.w, v.w);
    }

    const float inv = 1.0f / 64.0f;
    float4* o = reinterpret_cast<float4*>(g_am + (size_t)b * SS + 4 * (size_t)off4);
    o[0] = make_float4(s.x * inv, m.x, s.y * inv, m.y);
    o[1] = make_float4(s.z * inv, m.z, s.w * inv, m.w);
}

// ---------------------------------------------------------------------------
// Packed f32x2 helpers (sm_103a; ptxas will NOT auto-fuse — must be PTX).
// ---------------------------------------------------------------------------
__device__ __forceinline__ u64 ffma2(u64 a, u64 b, u64 c) {
    u64 d;
    asm("fma.rn.f32x2 %0, %1, %2, %3;" : "=l"(d) : "l"(a), "l"(b), "l"(c));
    return d;
}
__device__ __forceinline__ u64 pack2(float lo, float hi) {
    u64 r;
    asm("mov.b64 %0, {%1, %2};" : "=l"(r) : "f"(lo), "f"(hi));
    return r;
}
__device__ __forceinline__ float2 unpack2(u64 v) {
    float2 f;
    asm("mov.b64 {%0, %1}, %2;" : "=f"(f.x), "=f"(f.y) : "l"(v));
    return f;
}

// ---------------------------------------------------------------------------
// Pass 2: 3x3x3 SAME conv (avg,max -> 1 ch) + sigmoid.
// One thread = w-pair (w, w+1) x d-chunk of 4. No smem, no barriers.
// Sliding-plane: 6 fully-unrolled plane steps; per plane 12 LDG.64 (both
// channels per load) + 54 fma.rn.f32x2 (avg & max lanes in one instruction).
// Accumulator low lane = avg-channel partial, high lane = max-channel partial;
// summed once at output time.
// ---------------------------------------------------------------------------
#define DCK 4

__global__ __launch_bounds__(256, 2) void conv_kernel(const float* __restrict__ Wt,
                                                      float* __restrict__ out) {
    int g  = blockIdx.x * 256 + threadIdx.x;   // 0 .. 131071
    int wp = (g & 31) * 2;        // 0..62, even; outputs (wp, wp+1)
    int h  = (g >> 5) & 63;
    int dc = (g >> 11) & 7;
    int b  = g >> 14;
    int d0 = dc * DCK;

    // Packed weights: w2[kd*9 + kh*3 + kw] = (W_avg, W_max)
    u64 w2[27];
    #pragma unroll
    for (int j = 0; j < 27; ++j)
        w2[j] = pack2(__ldg(Wt + j), __ldg(Wt + 27 + j));

    const u64* gam = reinterpret_cast<const u64*>(g_am) + (size_t)b * SS;
    float*     ob  = out + (size_t)b * SS;

    const bool r0ok = (h > 0), r2ok = (h < 63);
    const bool c0ok = (wp > 0), c3ok = (wp < 62);

    // rotating accumulators: *0 -> out[p-1], *1 -> out[p]
    u64 aX0 = 0, aY0 = 0, aX1 = 0, aY1 = 0;

    #pragma unroll
    for (int s = 0; s < DCK + 2; ++s) {
        int p = d0 - 1 + s;
        u64 aX2 = 0, aY2 = 0;
        bool pok = (s >= 1 && s <= DCK) || ((unsigned)p < (unsigned)DD);
        if (pok) {
            const u64* pp = gam + p * PLANE + h * WW + wp;
            u64 v[3][4];
            #pragma unroll
            for (int kh = 0; kh < 3; ++kh) {
                bool rok = (kh == 0) ? r0ok : ((kh == 2) ? r2ok : true);
                const u64* rp = pp + (kh - 1) * WW;
                v[kh][0] = (rok && c0ok) ? __ldg(rp - 1) : 0ULL;
                v[kh][1] =  rok          ? __ldg(rp    ) : 0ULL;
                v[kh][2] =  rok          ? __ldg(rp + 1) : 0ULL;
                v[kh][3] = (rok && c3ok) ? __ldg(rp + 2) : 0ULL;
            }
            #pragma unroll
            for (int kh = 0; kh < 3; ++kh) {
                #pragma unroll
                for (int kw = 0; kw < 3; ++kw) {
                    const int i = kh * 3 + kw;
                    u64 vx = v[kh][kw];
                    u64 vy = v[kh][kw + 1];
                    aX0 = ffma2(vx, w2[18 + i], aX0);   // kd=2 -> out[p-1]
                    aY0 = ffma2(vy, w2[18 + i], aY0);
                    aX1 = ffma2(vx, w2[ 9 + i], aX1);   // kd=1 -> out[p]
                    aY1 = ffma2(vy, w2[ 9 + i], aY1);
                    aX2 = ffma2(vx, w2[     i], aX2);   // kd=0 -> out[p+1]
                    aY2 = ffma2(vy, w2[     i], aY2);
                }
            }
        }
        if (s >= 2) {
            int od = p - 1;                  // = d0 + s - 2, always in-chunk
            float2 fx = unpack2(aX0);
            float2 fy = unpack2(aY0);
            float sx = fx.x + fx.y;
            float sy = fy.x + fy.y;
            float2 o;
            o.x = 1.0f / (1.0f + __expf(-sx));
            o.y = 1.0f / (1.0f + __expf(-sy));
            *reinterpret_cast<float2*>(ob + od * PLANE + h * WW + wp) = o;
        }
        aX0 = aX1; aY0 = aY1;
        aX1 = aX2; aY1 = aY2;
    }
}

extern "C" void kernel_launch(void* const* d_in, const int* in_sizes, int n_in,
                              void* d_out, int out_size) {
    const float* x  = (const float*)d_in[0];   // [8,64,32,64,64] fp32
    const float* Wt = (const float*)d_in[1];   // [1,2,3,3,3]     fp32
    float* out = (float*)d_out;                // [8,1,32,64,64]  fp32
    (void)in_sizes; (void)n_in; (void)out_size;

    reduce_kernel<<<1024, 256>>>(x);
    conv_kernel<<<512, 256>>>(Wt, out);
}